// round 1
// baseline (speedup 1.0000x reference)
#include <cuda_runtime.h>

#define BB 8
#define TT 128
#define DD 256

// scratch: per-(b,t) contribution, reduced over t in pass 2 (deterministic, no atomics)
__device__ float g_part[BB * TT * DD];

__device__ __forceinline__ float ex2f(float x) {
    float y;
    asm("ex2.approx.f32 %0, %1;" : "=f"(y) : "f"(x));
    return y;
}

__global__ __launch_bounds__(DD) void attn_tile_kernel(
    const float* __restrict__ dec_t,   // [B, D]
    const float* __restrict__ enc_out  // [B, T, D]
) {
    __shared__ float s_dec[DD];  // dec[b,:] * log2(e)
    __shared__ float s_enc[DD];  // enc_out[b,t,:]

    const int bt = blockIdx.x;       // b*T + t
    const int b  = bt / TT;
    const int q  = threadIdx.x;

    const float L2E = 1.4426950408889634f;
    s_dec[q] = dec_t[b * DD + q] * L2E;
    s_enc[q] = enc_out[bt * DD + q];
    __syncthreads();

    const float x   = s_enc[q];  // enc_out[b,t,q]
    const float sdq = s_dec[q];  // dec[b,q] * log2e

    float cs = 0.0f;  // colsum[q] = sum_p exp(dec[p]*x)
    float rs = 0.0f;  // rowsum[q] = sum_r exp(dec[q]*enc[r])

#pragma unroll 8
    for (int p = 0; p < DD; p++) {
        cs += ex2f(s_dec[p] * x);
        rs += ex2f(sdq * s_enc[p]);
    }

    g_part[bt * DD + q] = x * cs / rs;
}

__global__ __launch_bounds__(256) void attn_reduce_kernel(float* __restrict__ out) {
    const int i = blockIdx.x * blockDim.x + threadIdx.x;  // b*D + q
    if (i >= BB * DD) return;
    const int b = i / DD;
    const int q = i - b * DD;

    float s = 0.0f;
#pragma unroll 8
    for (int t = 0; t < TT; t++) {
        s += g_part[(b * TT + t) * DD + q];
    }
    out[i] = s;
}

extern "C" void kernel_launch(void* const* d_in, const int* in_sizes, int n_in,
                              void* d_out, int out_size) {
    // Expected order: d_in[0] = dec_t [B,D] (2048), d_in[1] = enc_out [B,T,D] (262144).
    const float* dec_t   = (const float*)d_in[0];
    const float* enc_out = (const float*)d_in[1];
    if (n_in >= 2 && in_sizes[0] == BB * TT * DD && in_sizes[1] == BB * DD) {
        // defensive swap if metadata order differs
        dec_t   = (const float*)d_in[1];
        enc_out = (const float*)d_in[0];
    }
    float* out = (float*)d_out;

    attn_tile_kernel<<<BB * TT, DD>>>(dec_t, enc_out);
    attn_reduce_kernel<<<(BB * DD + 255) / 256, 256>>>(out);
}

// round 2
// speedup vs baseline: 1.2026x; 1.2026x over previous
#include <cuda_runtime.h>

#define BB 8
#define TT 128
#define DD 256
#define NW 8   // warps per block

// scratch: [b][q][t] layout so the reduce reads coalesced
__device__ float g_part[BB * DD * TT];

__device__ __forceinline__ float ex2f(float x) {
    float y;
    asm("ex2.approx.f32 %0, %1;" : "=f"(y) : "f"(x));
    return y;
}

__global__ __launch_bounds__(DD) void attn_tile_kernel(
    const float* __restrict__ dec_t,   // [B, D]
    const float* __restrict__ enc_out  // [B, T, D]
) {
    __shared__ float s_enc[DD];            // enc_out[b,t,:]
    __shared__ float s_colp[NW][DD];       // per-warp colsum partials

    const int bt = blockIdx.x;             // b*T + t
    const int b  = bt >> 7;                // / TT
    const int t  = bt & (TT - 1);
    const int tq = threadIdx.x;            // row p owned by this thread
    const int w  = tq >> 5;
    const int l  = tq & 31;

    const float L2E = 1.4426950408889634f;
    const float d   = dec_t[b * DD + tq] * L2E;  // log2e-prescaled dec for row p=tq
    const float ev  = enc_out[bt * DD + tq];
    s_enc[tq] = ev;
    __syncthreads();

    float rs = 0.0f;  // rowsum for row p = tq (stays in this lane)
    const int nl = l + 1;  // shfl srcLane wraps mod 32 automatically

    for (int J = 0; J < NW; J++) {
        // lane l starts with column 32J+l of this slab; enc value rotates in regs
        float enc_c = s_enc[J * 32 + l];
        float acc   = 0.0f;   // colsum token; starts (and ends) at lane l => column 32J+l
#pragma unroll
        for (int k = 0; k < 32; k++) {
            float e = ex2f(d * enc_c);
            rs  += e;          // row p=tq, column (32J + (l+k)&31): covers slab once
            acc += e;          // token at lane m adds col 32J+m0 (constant per token)
            acc   = __shfl_sync(0xffffffffu, acc,   nl, 32);
            enc_c = __shfl_sync(0xffffffffu, enc_c, nl, 32);
        }
        s_colp[w][J * 32 + l] = acc;  // warp-w partial colsum for column 32J+l
    }
    __syncthreads();

    float cs = 0.0f;
#pragma unroll
    for (int w2 = 0; w2 < NW; w2++) cs += s_colp[w2][tq];

    g_part[(b * DD + tq) * TT + t] = __fdividef(ev * cs, rs);
}

__global__ __launch_bounds__(TT) void attn_reduce_kernel(float* __restrict__ out) {
    const int bq = blockIdx.x;       // b*D + q  (matches out layout)
    const int t  = threadIdx.x;

    float v = g_part[bq * TT + t];   // coalesced 512B per block
#pragma unroll
    for (int s = 16; s > 0; s >>= 1)
        v += __shfl_xor_sync(0xffffffffu, v, s, 32);

    __shared__ float sp[4];
    if ((t & 31) == 0) sp[t >> 5] = v;
    __syncthreads();
    if (t == 0) out[bq] = (sp[0] + sp[1]) + (sp[2] + sp[3]);
}

extern "C" void kernel_launch(void* const* d_in, const int* in_sizes, int n_in,
                              void* d_out, int out_size) {
    const float* dec_t   = (const float*)d_in[0];
    const float* enc_out = (const float*)d_in[1];
    if (n_in >= 2 && in_sizes[0] == BB * TT * DD && in_sizes[1] == BB * DD) {
        dec_t   = (const float*)d_in[1];
        enc_out = (const float*)d_in[0];
    }
    float* out = (float*)d_out;

    attn_tile_kernel<<<BB * TT, DD>>>(dec_t, enc_out);
    attn_reduce_kernel<<<BB * DD, TT>>>(out);
}

// round 3
// speedup vs baseline: 1.3222x; 1.0994x over previous
#include <cuda_runtime.h>

#define BB 8
#define TT 128
#define DD 256
#define NW 8   // warps per block

// scratch: [b][q][t] layout so the reduce reads coalesced float4 per warp
__device__ __align__(16) float g_part[BB * DD * TT];

__device__ __forceinline__ float ex2f(float x) {
    float y;
    asm("ex2.approx.f32 %0, %1;" : "=f"(y) : "f"(x));
    return y;
}

__global__ __launch_bounds__(DD) void attn_tile_kernel(
    const float* __restrict__ dec_t,   // [B, D]
    const float* __restrict__ enc_out  // [B, T, D]
) {
    __shared__ float s_dec[DD];          // dec[b,:] * log2(e)
    __shared__ float s_rowp[NW][DD];     // per-colgroup rowsum partials

    const int bt = blockIdx.x;           // b*T + t
    const int b  = bt >> 7;
    const int t  = bt & (TT - 1);
    const int tq = threadIdx.x;          // this thread's column q (and row for rowsum)
    const int w  = tq >> 5;              // column group of this warp
    const int l  = tq & 31;

    const float L2E = 1.4426950408889634f;
    s_dec[tq]      = dec_t[b * DD + tq] * L2E;
    const float x  = enc_out[bt * DD + tq];   // enc value for column q = tq
    __syncthreads();

    float cs = 0.0f;                     // colsum[tq] = sum_p E[p][tq]

    // Warp w sweeps row-groups g: block rows 32g..32g+31, cols 32w..32w+31.
    // Step k: lane l computes E[32g + l^k][32w + l] once; it contributes to
    //   colsum of its own column directly, and (via shfl.xor by k) the
    //   transpose-partner lane receives its row term. No E entry computed twice,
    //   no loop-carried shfl chain.
    for (int g = 0; g < NW; g++) {
        const float* dg = &s_dec[g * 32];
        float rp = 0.0f;                 // rowsum partial for row 32g+l over cols of group w
#pragma unroll
        for (int k = 0; k < 32; k++) {
            float e  = ex2f(dg[l ^ k] * x);     // E[32g+l^k][32w+l]
            cs      += e;
            float rr = __shfl_xor_sync(0xffffffffu, e, k, 32);  // E[32g+l][32w+l^k]
            rp      += rr;
        }
        s_rowp[w][g * 32 + l] = rp;
    }
    __syncthreads();

    float rs = 0.0f;                     // rowsum[tq] = sum_c E[tq][c]
#pragma unroll
    for (int w2 = 0; w2 < NW; w2++) rs += s_rowp[w2][tq];

    g_part[(b * DD + tq) * TT + t] = __fdividef(x * cs, rs);
}

// warp per (b,q) row: 32 lanes x float4 = 128 t-values, coalesced 512B
__global__ __launch_bounds__(256) void attn_reduce_kernel(float* __restrict__ out) {
    const int warp = (blockIdx.x * 256 + threadIdx.x) >> 5;   // 0..2047 = b*D+q
    const int l    = threadIdx.x & 31;

    const float4 v = ((const float4*)(g_part + warp * TT))[l];
    float s = (v.x + v.y) + (v.z + v.w);
#pragma unroll
    for (int k = 16; k > 0; k >>= 1)
        s += __shfl_xor_sync(0xffffffffu, s, k, 32);
    if (l == 0) out[warp] = s;
}

extern "C" void kernel_launch(void* const* d_in, const int* in_sizes, int n_in,
                              void* d_out, int out_size) {
    const float* dec_t   = (const float*)d_in[0];
    const float* enc_out = (const float*)d_in[1];
    if (n_in >= 2 && in_sizes[0] == BB * TT * DD && in_sizes[1] == BB * DD) {
        dec_t   = (const float*)d_in[1];
        enc_out = (const float*)d_in[0];
    }
    float* out = (float*)d_out;

    attn_tile_kernel<<<BB * TT, DD>>>(dec_t, enc_out);
    attn_reduce_kernel<<<(BB * DD * 32) / 256, 256>>>(out);
}

// round 5
// speedup vs baseline: 1.5186x; 1.1486x over previous
#include <cuda_runtime.h>

#define BB 8
#define TT 128
#define DD 256

__device__ __forceinline__ float ex2f(float x) {
    float y;
    asm("ex2.approx.f32 %0, %1;" : "=f"(y) : "f"(x));
    return y;
}

// One block per (b,t). Thread tid: owns columns 4*(tid&63)..+3 and row-part tid>>6.
// Each E entry computed ONCE (1 MUFU); row transport amortized 4:1 via pre-reduced
// smem partials (1 STS per 4 entries). Output fused via atomicAdd over t.
__global__ __launch_bounds__(256) void attn_fused_kernel(
    const float* __restrict__ dec_t,   // [B, D]
    const float* __restrict__ enc_out, // [B, T, D]
    float* __restrict__ out            // [B, D], pre-zeroed
) {
    __shared__ float s_dec[DD];          // dec * log2e
    __shared__ float s_enc[DD];
    __shared__ float s_rp[64][68];       // row partials for current 64-row chunk (padded)
    __shared__ float s_rowsum[DD];
    __shared__ float s_colp[4][DD];      // per-rowpart colsum partials

    const int bt  = blockIdx.x;          // b*T + t
    const int b   = bt >> 7;
    const int tid = threadIdx.x;
    const int cg  = tid & 63;            // column group: cols 4cg..4cg+3
    const int rp  = tid >> 6;            // row part 0..3 (rows rp*16..rp*16+15 of each chunk)

    const float L2E = 1.4426950408889634f;
    s_dec[tid] = dec_t[b * DD + tid] * L2E;
    s_enc[tid] = enc_out[bt * DD + tid];
    __syncthreads();

    const float4 xv = *(const float4*)&s_enc[cg * 4];   // this thread's 4 enc values
    float cs0 = 0.f, cs1 = 0.f, cs2 = 0.f, cs3 = 0.f;

    const int rrow = tid >> 2;           // reduce-phase: row 0..63 of chunk
    const int rqx  = tid & 3;            // quarter of that row

    for (int c = 0; c < 4; c++) {        // 4 chunks of 64 rows
        const int pbase = c * 64 + rp * 16;
#pragma unroll
        for (int i = 0; i < 16; i++) {
            const float d  = s_dec[pbase + i];          // broadcast LDS
            const float e0 = ex2f(d * xv.x);
            const float e1 = ex2f(d * xv.y);
            const float e2 = ex2f(d * xv.z);
            const float e3 = ex2f(d * xv.w);
            cs0 += e0; cs1 += e1; cs2 += e2; cs3 += e3;
            s_rp[rp * 16 + i][cg] = (e0 + e1) + (e2 + e3);  // conflict-free STS
        }
        __syncthreads();

        // rowsum for the 64 chunk rows: 4 threads per row, float4 loads
        const float4* rowq = (const float4*)&s_rp[rrow][rqx * 16];
        const float4 a0 = rowq[0], a1 = rowq[1], a2 = rowq[2], a3 = rowq[3];
        float s = ((a0.x + a0.y) + (a0.z + a0.w)) + ((a1.x + a1.y) + (a1.z + a1.w))
                + ((a2.x + a2.y) + (a2.z + a2.w)) + ((a3.x + a3.y) + (a3.z + a3.w));
        s += __shfl_xor_sync(0xffffffffu, s, 1, 32);
        s += __shfl_xor_sync(0xffffffffu, s, 2, 32);
        if (rqx == 0) s_rowsum[c * 64 + rrow] = s;
        __syncthreads();                 // protect s_rp for next chunk
    }

    // combine colsum partials across the 4 row-parts
    *((float4*)&s_colp[rp][cg * 4]) = make_float4(cs0, cs1, cs2, cs3);
    __syncthreads();

    const int q  = tid;
    const float cs = (s_colp[0][q] + s_colp[1][q]) + (s_colp[2][q] + s_colp[3][q]);
    const float rs = s_rowsum[q];
    const float v  = __fdividef(s_enc[q] * cs, rs);
    atomicAdd(&out[b * DD + q], v);      // accumulate over t (128 blocks per address)
}

extern "C" void kernel_launch(void* const* d_in, const int* in_sizes, int n_in,
                              void* d_out, int out_size) {
    const float* dec_t   = (const float*)d_in[0];
    const float* enc_out = (const float*)d_in[1];
    if (n_in >= 2 && in_sizes[0] == BB * TT * DD && in_sizes[1] == BB * DD) {
        dec_t   = (const float*)d_in[1];
        enc_out = (const float*)d_in[0];
    }
    float* out = (float*)d_out;

    cudaMemsetAsync(out, 0, BB * DD * sizeof(float), 0);
    attn_fused_kernel<<<BB * TT, DD>>>(dec_t, enc_out, out);
}

// round 9
// speedup vs baseline: 1.5977x; 1.0521x over previous
#include <cuda_runtime.h>

#define BB 8
#define TT 128
#define DD 256
#define PAD 33

typedef unsigned long long u64;

__device__ __forceinline__ float ex2f(float x) {
    float y; asm("ex2.approx.f32 %0, %1;" : "=f"(y) : "f"(x)); return y;
}
__device__ __forceinline__ u64 pk(float a, float b) {
    u64 r; asm("mov.b64 %0, {%1, %2};" : "=l"(r) : "f"(a), "f"(b)); return r;
}
__device__ __forceinline__ float2 upk(u64 p) {
    float2 v; asm("mov.b64 {%0, %1}, %2;" : "=f"(v.x), "=f"(v.y) : "l"(p)); return v;
}
__device__ __forceinline__ u64 padd(u64 a, u64 b) {
    u64 r; asm("add.rn.f32x2 %0, %1, %2;" : "=l"(r) : "l"(a), "l"(b)); return r;
}
__device__ __forceinline__ u64 pmul(u64 a, u64 b) {
    u64 r; asm("mul.rn.f32x2 %0, %1, %2;" : "=l"(r) : "l"(a), "l"(b)); return r;
}

// One block per (b,t). Thread tid = (rp, cg): owns cols 8cg..8cg+7 for all rows,
// and rows 32rp..32rp+31 for row-partial production. Each E entry: 1 MUFU +
// 0.5 packed-mul + ~0.9 packed-add + 1/8 STS. Two syncthreads total.
__global__ __launch_bounds__(DD) void attn_fused_kernel(
    const float* __restrict__ dec_t,   // [B, D]
    const float* __restrict__ enc_out, // [B, T, D]
    float* __restrict__ out            // [B, D], pre-zeroed
) {
    __shared__ float s_dec[DD];          // dec * log2e
    __shared__ float s_rp[DD][PAD];      // row partials: [row][colgroup]
    __shared__ float s_cp[8][DD];        // colsum partials: [rowpart][col]

    const int bt  = blockIdx.x;          // b*T + t
    const int b   = bt >> 7;
    const int tid = threadIdx.x;
    const int cg  = tid & 31;            // col group (8 cols)
    const int rp  = tid >> 5;            // row part (32 rows)

    const float L2E = 1.4426950408889634f;
    s_dec[tid] = dec_t[b * DD + tid] * L2E;

    // this thread's 8 enc values, kept as 4 packed f32x2
    const float4 xa = *(const float4*)(enc_out + bt * DD + cg * 8);
    const float4 xb = *(const float4*)(enc_out + bt * DD + cg * 8 + 4);
    const u64 px0 = pk(xa.x, xa.y), px1 = pk(xa.z, xa.w);
    const u64 px2 = pk(xb.x, xb.y), px3 = pk(xb.z, xb.w);

    __syncthreads();

    u64 c0 = 0ull, c1 = 0ull, c2 = 0ull, c3 = 0ull;  // packed (0.f,0.f)

    const int pbase = rp * 32;
#pragma unroll 8
    for (int i = 0; i < 32; i++) {
        const float d  = s_dec[pbase + i];           // uniform per warp -> broadcast
        const u64   dd = pk(d, d);
        const float2 f0 = upk(pmul(dd, px0));
        const float2 f1 = upk(pmul(dd, px1));
        const float2 f2 = upk(pmul(dd, px2));
        const float2 f3 = upk(pmul(dd, px3));
        const u64 p0 = pk(ex2f(f0.x), ex2f(f0.y));
        const u64 p1 = pk(ex2f(f1.x), ex2f(f1.y));
        const u64 p2 = pk(ex2f(f2.x), ex2f(f2.y));
        const u64 p3 = pk(ex2f(f3.x), ex2f(f3.y));
        c0 = padd(c0, p0); c1 = padd(c1, p1);
        c2 = padd(c2, p2); c3 = padd(c3, p3);
        const float2 qq = upk(padd(padd(p0, p1), padd(p2, p3)));
        s_rp[pbase + i][cg] = qq.x + qq.y;           // bank = (row + cg) % 32: conflict-free
    }

    // spill packed colsum partials for cross-rowpart combine
    {
        const float2 a0 = upk(c0), a1 = upk(c1), a2 = upk(c2), a3 = upk(c3);
        float* dst = &s_cp[rp][cg * 8];
        dst[0] = a0.x; dst[1] = a0.y; dst[2] = a1.x; dst[3] = a1.y;
        dst[4] = a2.x; dst[5] = a2.y; dst[6] = a3.x; dst[7] = a3.y;
    }
    __syncthreads();

    // rowsum of row tid — same thread that outputs column q = tid, so no smem round-trip
    float rs = 0.0f;
#pragma unroll
    for (int j = 0; j < 32; j++) rs += s_rp[tid][j]; // bank = (tid + j) % 32: conflict-free

    float cs = 0.0f;
#pragma unroll
    for (int r = 0; r < 8; r++) cs += s_cp[r][tid];  // lane-distinct banks

    const float x = enc_out[bt * DD + tid];
    atomicAdd(&out[b * DD + tid], __fdividef(x * cs, rs));
}

extern "C" void kernel_launch(void* const* d_in, const int* in_sizes, int n_in,
                              void* d_out, int out_size) {
    const float* dec_t   = (const float*)d_in[0];
    const float* enc_out = (const float*)d_in[1];
    if (n_in >= 2 && in_sizes[0] == BB * TT * DD && in_sizes[1] == BB * DD) {
        dec_t   = (const float*)d_in[1];
        enc_out = (const float*)d_in[0];
    }
    float* out = (float*)d_out;

    cudaMemsetAsync(out, 0, BB * DD * sizeof(float), 0);
    attn_fused_kernel<<<BB * TT, DD>>>(dec_t, enc_out, out);
}